// round 4
// baseline (speedup 1.0000x reference)
#include <cuda_runtime.h>

#define N_    16
#define C_    512
#define GRP   4
#define CG    128
#define MIP   16
#define EPS_  1e-5f

#define CLUSTER 16          // CTAs per (n,g) group
#define CPC     8           // channels (tiles) per CTA
#define TPB     512

// Pooled values, cluster-shared via L2: [group][c_in_group][l]  (4 MB)
__device__ float g_pool[N_ * GRP][CG][128];

// Dynamic smem layout (floats)
#define TILE_STRIDE 4160                 // 64*65 padded tile
#define SM_TILES    0
#define SM_W1       (CPC * TILE_STRIDE)  // 33280
#define SM_YS       (SM_W1 + MIP * CG)   // +2048
#define SM_SAH      (SM_YS + MIP * 128)  // +2048
#define SM_SAW      (SM_SAH + CPC * 64)  // +512
#define SMEM_FLOATS (SM_SAW + CPC * 64)  // +512  => 38400 floats = 153600 B

__global__ void __launch_bounds__(TPB, 1) fused_kernel(
    const float* __restrict__ x,
    const float* __restrict__ W1, const float* __restrict__ b1,
    const float* __restrict__ gamma, const float* __restrict__ beta,
    const float* __restrict__ mean_, const float* __restrict__ var_,
    const float* __restrict__ Wh, const float* __restrict__ bh,
    const float* __restrict__ Ww, const float* __restrict__ bw,
    float* __restrict__ out)
{
    extern __shared__ float sm[];
    const int tid  = threadIdx.x;
    const int grp  = blockIdx.x >> 4;        // 0..63  (n*4+g)
    const int rank = blockIdx.x & (CLUSTER - 1);
    const int n    = grp >> 2, g = grp & 3;
    const int ch0  = g * CG + rank * CPC;    // first channel (within 512) of this CTA

    // Preload W1 into smem (overlaps with tile loads)
    for (int i = tid; i < MIP * CG; i += TPB) sm[SM_W1 + i] = W1[i];

    // ---- phase A: load 8 tiles (128 KB) into padded smem ----
    const float4* __restrict__ xp =
        (const float4*)(x + ((size_t)n * C_ + ch0) * 4096);
#pragma unroll 8
    for (int k = 0; k < 16; k++) {
        int idx4 = k * TPB + tid;
        float4 v = xp[idx4];
        int t = idx4 >> 10;
        int f = (idx4 & 1023) << 2;
        int h = f >> 6, w = f & 63;
        float* p = &sm[SM_TILES + t * TILE_STRIDE + h * 65 + w];
        p[0] = v.x; p[1] = v.y; p[2] = v.z; p[3] = v.w;
    }
    __syncthreads();

    // ---- pooling: 8 tiles x (64 rows + 64 cols) = 1024 tasks, 2/thread ----
#pragma unroll
    for (int q = 0; q < 2; q++) {
        int task = q * TPB + tid;
        int t = task >> 7;
        int r = task & 127;
        const float* base = &sm[SM_TILES + t * TILE_STRIDE];
        float s0 = 0.f, s1 = 0.f;
        if (r < 64) {
#pragma unroll
            for (int i = 0; i < 64; i += 2) { s0 += base[r * 65 + i]; s1 += base[r * 65 + i + 1]; }
        } else {
            int w = r - 64;
#pragma unroll
            for (int i = 0; i < 64; i += 2) { s0 += base[i * 65 + w]; s1 += base[(i + 1) * 65 + w]; }
        }
        g_pool[grp][rank * CPC + t][r] = (s0 + s1) * (1.f / 64.f);
    }

    // publish pooled values to the cluster, then barrier
    __threadfence();
    asm volatile("barrier.cluster.arrive.aligned;" ::: "memory");
    asm volatile("barrier.cluster.wait.aligned;" ::: "memory");

    // ---- phase B1: y[m][l] redundantly per CTA. thread = (mg, l) ----
    {
        int l  = tid & 127;
        int mg = tid >> 7;                    // 0..3 -> m in [mg*4, mg*4+4)
        float acc0 = 0.f, acc1 = 0.f, acc2 = 0.f, acc3 = 0.f;
        const float* pw = &sm[SM_W1 + (mg * 4) * CG];
        const float* pp = &g_pool[grp][0][l];
#pragma unroll 4
        for (int c = 0; c < CG; c++) {
            float v = pp[(size_t)c * 128];    // coalesced across l
            acc0 += pw[c] * v;
            acc1 += pw[CG + c] * v;
            acc2 += pw[2 * CG + c] * v;
            acc3 += pw[3 * CG + c] * v;
        }
        float accs[4] = {acc0, acc1, acc2, acc3};
#pragma unroll
        for (int j = 0; j < 4; j++) {
            int m = mg * 4 + j;
            float sc = gamma[m] * rsqrtf(var_[m] + EPS_);
            float v = (accs[j] + b1[m]) * sc + (beta[m] - mean_[m] * sc);
            float r = fminf(fmaxf(v + 3.f, 0.f), 6.f);   // hard-swish
            sm[SM_YS + m * 128 + l] = v * r * (1.f / 6.f);
        }
    }
    __syncthreads();

    // ---- phase B2: gates for own 8 channels. thread = (ci, l) ----
    {
        int ci = tid >> 6;                    // 0..7
        int l  = tid & 63;
        int c_in_g = rank * CPC + ci;
        float sh = bh[c_in_g], sw2 = bw[c_in_g];
#pragma unroll
        for (int m = 0; m < MIP; m++) {
            sh  += Wh[c_in_g * MIP + m] * sm[SM_YS + m * 128 + l];
            sw2 += Ww[c_in_g * MIP + m] * sm[SM_YS + m * 128 + 64 + l];
        }
        sm[SM_SAH + ci * 64 + l] = 1.f / (1.f + __expf(-sh));
        sm[SM_SAW + ci * 64 + l] = 1.f / (1.f + __expf(-sw2));
    }
    __syncthreads();

    // ---- phase C: apply gates to smem tiles, shuffled write ----
#pragma unroll 8
    for (int k = 0; k < 16; k++) {
        int idx4 = k * TPB + tid;
        int t = idx4 >> 10;
        int within = idx4 & 1023;
        int f = within << 2;
        int h = f >> 6, w = f & 63;
        const float* p = &sm[SM_TILES + t * TILE_STRIDE + h * 65 + w];
        const float a = sm[SM_SAH + t * 64 + h];
        float4 v;
        v.x = p[0] * a * sm[SM_SAW + t * 64 + w];
        v.y = p[1] * a * sm[SM_SAW + t * 64 + w + 1];
        v.z = p[2] * a * sm[SM_SAW + t * 64 + w + 2];
        v.w = p[3] * a * sm[SM_SAW + t * 64 + w + 3];
        int ch = ch0 + t;
        int fc = (ch & 3) * 128 + (ch >> 2);   // channel shuffle
        float4* __restrict__ op = (float4*)(out + ((size_t)n * C_ + fc) * 4096);
        op[within] = v;
    }
}

extern "C" void kernel_launch(void* const* d_in, const int* in_sizes, int n_in,
                              void* d_out, int out_size) {
    const float* x     = (const float*)d_in[0];
    const float* W1    = (const float*)d_in[1];
    const float* b1    = (const float*)d_in[2];
    const float* gamma = (const float*)d_in[3];
    const float* beta  = (const float*)d_in[4];
    const float* mean_ = (const float*)d_in[5];
    const float* var_  = (const float*)d_in[6];
    const float* Wh    = (const float*)d_in[7];
    const float* bh    = (const float*)d_in[8];
    const float* Ww    = (const float*)d_in[9];
    const float* bw    = (const float*)d_in[10];
    float* out = (float*)d_out;

    cudaFuncSetAttribute(fused_kernel,
                         cudaFuncAttributeMaxDynamicSharedMemorySize,
                         SMEM_FLOATS * sizeof(float));
    cudaFuncSetAttribute(fused_kernel,
                         cudaFuncAttributeNonPortableClusterSizeAllowed, 1);

    cudaLaunchConfig_t cfg = {};
    cfg.gridDim  = dim3(N_ * GRP * CLUSTER, 1, 1);   // 1024 CTAs = 64 clusters
    cfg.blockDim = dim3(TPB, 1, 1);
    cfg.dynamicSmemBytes = SMEM_FLOATS * sizeof(float);
    cfg.stream = 0;

    cudaLaunchAttribute attrs[1];
    attrs[0].id = cudaLaunchAttributeClusterDimension;
    attrs[0].val.clusterDim = {CLUSTER, 1, 1};
    cfg.attrs = attrs;
    cfg.numAttrs = 1;

    cudaLaunchKernelEx(&cfg, fused_kernel,
                       x, W1, b1, gamma, beta, mean_, var_,
                       Wh, bh, Ww, bw, out);
}